// round 6
// baseline (speedup 1.0000x reference)
#include <cuda_runtime.h>

#define T_STEPS 730
#define N_GRID  8000
#define NZ      1e-5f

__constant__ float c_LO[18] = {-3.f, 0.f, 0.f, 0.f, 0.f, 0.f, 0.f, 0.f, 0.005f, 1.f, 0.f, 1.f, 0.f, 1.f, 0.f, 0.f, 0.f, 0.f};
__constant__ float c_HI[18] = { 5.f,20.f, 1.f, 1.f, 5.f,50.f, 1.f, 1.f, 0.995f, 2000.f, 20.f, 300.f, 1.f, 5.f, 1.f, 1.f, 1.f, 1.f};

__global__ __launch_bounds__(64) void prms_kernel(
    const float* __restrict__ x,      // [T_STEPS, N_GRID, 3]
    const float* __restrict__ params, // [T_STEPS, N_GRID, 18]
    float* __restrict__ out)          // [T_STEPS, N_GRID]
{
    const int g = blockIdx.x * blockDim.x + threadIdx.x;
    if (g >= N_GRID) return;

    // ---- per-cell parameters from the LAST timestep slice ----
    const float* pp = params + ((size_t)(T_STEPS - 1) * N_GRID + g) * 18;
    float pr[18];
#pragma unroll
    for (int i = 0; i < 18; i++) {
        float s = 1.0f / (1.0f + expf(-pp[i]));
        pr[i] = c_LO[i] + s * (c_HI[i] - c_LO[i]);
    }
    const float tt     = pr[0],  ddf   = pr[1],  alpha = pr[2],  beta  = pr[3];
    const float stor   = pr[4],  retip = pr[5],  fscn  = pr[6],  scx   = pr[7];
    const float flz    = pr[8],  stot  = pr[9],  cgw   = pr[10], resmax= pr[11];
    const float k1     = pr[12], k2    = pr[13], k3    = pr[14], k4    = pr[15];
    const float k5     = pr[16], k6    = pr[17];

    const float scn        = fscn * scx;
    const float remx       = (1.0f - flz) * stot;
    const float smax       = flz * stot;
    const float inv_remx   = 1.0f / remx;
    const float inv_smax   = 1.0f / smax;
    const float inv_resmax = 1.0f / resmax;
    const float omb        = 1.0f - beta;
    const float oma        = 1.0f - alpha;
    const float c2         = (scx - scn) * inv_remx;   // sro_lin slope

    // ---- state ----
    float snow = 0.001f, xin = 0.001f, rstor = 0.001f, rechr = 0.001f;
    float smav = 0.001f, res = 0.001f, gw = 0.001f;

    // ---- depth-4 rotating forcing buffer: slot t&3 holds x[t] ----
    float Pb[4], Tb[4], Eb[4];
#pragma unroll
    for (int t = 0; t < 4; t++) {
        const float* xt = x + ((size_t)t * N_GRID + g) * 3;
        Pb[t] = xt[0]; Tb[t] = xt[1]; Eb[t] = xt[2];
    }

#pragma unroll 4
    for (int t = 0; t < T_STEPS; t++) {
        const int b = t & 3;
        // snapshot current forcing, then refill slot with t+4 (clamped index: no OOB)
        const float P  = Pb[b];
        const float Tm = Tb[b];
        const float Ep = Eb[b];
        {
            const int tn = (t + 4 < T_STEPS) ? (t + 4) : (T_STEPS - 1);
            const float* xn = x + ((size_t)tn * N_GRID + g) * 3;
            Pb[b] = xn[0]; Tb[b] = xn[1]; Eb[b] = xn[2];
        }

        // ---- off-chain forcing functions ----
        const float mpot = fmaxf(ddf * (Tm - tt), 0.0f);          // potential melt
        const float ps   = (Tm <= tt) ? P : 0.0f;
        const float prr  = P - ps;
        const float pim  = prr * omb;
        const float psm  = prr * beta;
        const float pby  = psm * oma;
        const float pin  = psm * alpha;
        const float epb  = Ep * beta;
        const float eib  = Ep * omb;

        // ---- snow (depth-3 self-loop) ----
        const float snow1  = snow + ps;
        const float flux_m = fminf(mpot, snow1);
        snow = fmaxf(snow1 - mpot, NZ);                            // lemma: == max(snow1-flux_m, NZ)

        // ---- interception ----
        const float xin1 = xin + pin;
        const float xin2 = fminf(xin1, stor);                      // == xin1 - ptf (clamped)
        const float ptf  = fmaxf(xin1 - stor, 0.0f);
        const float ein  = fminf(epb, xin2);
        xin = fmaxf(xin2 - epb, NZ);                               // lemma

        // ---- impervious storage ----
        const float rs1 = rstor + fmaf(flux_m, omb, pim);          // + mim + pim
        const float rs2 = fminf(rs1, retip);
        const float sas = fmaxf(rs1 - retip, 0.0f);
        const float eim = fminf(eib, rs2);
        rstor = fmaxf(rs2 - eib, NZ);                              // lemma

        const float epnet = Ep - ein - eim;                        // >= 0 always

        // ---- surface runoff / recharge ----
        const float srol   = fminf(fmaxf(fmaf(c2, rechr, scn), 0.0f), 1.0f);
        const float inflow = fmaf(flux_m, beta, ptf) + pby;
        const float sro    = srol * inflow;
        const float inf    = inflow - sro;
        const float re1    = rechr + inf;
        const float re2    = fminf(re1, remx);
        const float pc     = fmaxf(re1 - remx, 0.0f);
        const float aa     = inv_remx * epnet;                     // >= 0
        const float ea     = fminf(re2 * aa, re2);
        rechr = fmaxf(re2 - ea, NZ);

        // ---- soil moisture ----
        const float sm1   = smav + pc;
        const float sm2   = fminf(sm1, smax);
        const float excs  = fmaxf(sm1 - smax, 0.0f);
        const float tmax  = fmaxf(sm2 * inv_smax * (epnet - ea), 0.0f);
        const float transp = (rechr < epnet) ? fminf(tmax, sm2) : 0.0f;
        smav = fmaxf(sm2 - transp, NZ);

        // ---- reservoir ----
        const float sep  = fminf(cgw, excs);
        const float qres = excs - sep;                             // >= 0 exactly
        const float r1   = res + qres;
        const float ratio = r1 * inv_resmax;
        const float gad  = fminf(k1 * powf(ratio, k2), r1);
        const float r2   = fmaxf(r1 - gad, NZ);
        const float rasm = fminf(fmaf(k4, r2, k3), 1.0f);
        const float ras  = r2 * rasm;
        res = fmaxf(r2 - ras, NZ);

        // ---- groundwater ----
        const float g1  = gw + gad + sep;
        const float bas = k5 * g1;
        const float g2  = fmaxf(g1 - bas, NZ);
        gw = fmaxf(g2 - k6 * g2, NZ);

        // ---- streamflow ----
        out[(size_t)t * N_GRID + g] = (sas + sro) + (bas + ras);
    }
}

extern "C" void kernel_launch(void* const* d_in, const int* in_sizes, int n_in,
                              void* d_out, int out_size) {
    // Identify inputs by element count (robust to ordering):
    //   x:          730*8000*3  = 17,520,000
    //   parameters: 730*8000*18 = 105,120,000
    const float* x = nullptr;
    const float* params = nullptr;
    for (int i = 0; i < n_in; i++) {
        if (in_sizes[i] == T_STEPS * N_GRID * 3)  x = (const float*)d_in[i];
        if (in_sizes[i] == T_STEPS * N_GRID * 18) params = (const float*)d_in[i];
    }
    float* out = (float*)d_out;

    const int threads = 64;
    const int blocks = (N_GRID + threads - 1) / threads;   // 125 blocks, 250 warps
    prms_kernel<<<blocks, threads>>>(x, params, out);
}

// round 7
// speedup vs baseline: 1.6487x; 1.6487x over previous
#include <cuda_runtime.h>

#define T_STEPS 730
#define N_GRID  8000
#define NZ      1e-5f

__constant__ float c_LO[18] = {-3.f, 0.f, 0.f, 0.f, 0.f, 0.f, 0.f, 0.f, 0.005f, 1.f, 0.f, 1.f, 0.f, 1.f, 0.f, 0.f, 0.f, 0.f};
__constant__ float c_HI[18] = { 5.f,20.f, 1.f, 1.f, 5.f,50.f, 1.f, 1.f, 0.995f, 2000.f, 20.f, 300.f, 1.f, 5.f, 1.f, 1.f, 1.f, 1.f};

__global__ __launch_bounds__(64) void prms_kernel(
    const float* __restrict__ x,      // [T_STEPS, N_GRID, 3]
    const float* __restrict__ params, // [T_STEPS, N_GRID, 18]
    float* __restrict__ out)          // [T_STEPS, N_GRID]
{
    const int g = blockIdx.x * blockDim.x + threadIdx.x;
    if (g >= N_GRID) return;

    // ---- per-cell parameters from the LAST timestep slice ----
    const float* pp = params + ((size_t)(T_STEPS - 1) * N_GRID + g) * 18;
    float pr[18];
#pragma unroll
    for (int i = 0; i < 18; i++) {
        float s = 1.0f / (1.0f + expf(-pp[i]));
        pr[i] = c_LO[i] + s * (c_HI[i] - c_LO[i]);
    }
    const float tt     = pr[0],  ddf   = pr[1],  alpha = pr[2],  beta  = pr[3];
    const float stor   = pr[4],  retip = pr[5],  fscn  = pr[6],  scx   = pr[7];
    const float flz    = pr[8],  stot  = pr[9],  cgw   = pr[10], resmax= pr[11];
    const float k1     = pr[12], k2    = pr[13], k3    = pr[14], k4    = pr[15];
    const float k5     = pr[16], k6    = pr[17];

    const float scn        = fscn * scx;
    const float remx       = (1.0f - flz) * stot;
    const float smax       = flz * stot;
    const float inv_remx   = 1.0f / remx;
    const float inv_smax   = 1.0f / smax;
    const float inv_resmax = 1.0f / resmax;
    const float one_m_beta = 1.0f - beta;
    const float one_m_alpha= 1.0f - alpha;
    const float c2         = (scx - scn) * inv_remx;   // sro_lin slope (pre-divided)
    const float lg2k1      = log2f(k1);                // fold k1 into pow exponent

    // ---- state ----
    float snow = 0.001f, xin = 0.001f, rstor = 0.001f, rechr = 0.001f;
    float smav = 0.001f, res = 0.001f, gw = 0.001f;

    // ---- depth-2 register prefetch pipeline for x (identical to R1) ----
    float Pb[2], Tb[2], Eb[2];
    {
        const float* x0 = x + (size_t)g * 3;                      // t = 0
        Pb[0] = x0[0]; Tb[0] = x0[1]; Eb[0] = x0[2];
        const float* x1 = x + ((size_t)N_GRID + g) * 3;           // t = 1
        Pb[1] = x1[0]; Tb[1] = x1[1]; Eb[1] = x1[2];
    }

    // strength-reduced pointers
    const float* xp = x + ((size_t)2 * N_GRID + g) * 3;   // points at x[t+2] forcing
    float*       op = out + g;                            // points at out[t]

#pragma unroll 2
    for (int t = 0; t < T_STEPS; t++) {
        const int b = t & 1;
        // read current forcing FIRST (R1 ordering), then prefetch t+2
        const float P  = Pb[b];
        const float Tc = Tb[b];
        const float Ep = Eb[b];

        if (t + 2 < T_STEPS) {
            Pb[b] = xp[0]; Tb[b] = xp[1]; Eb[b] = xp[2];
        }
        xp += (size_t)N_GRID * 3;

        // ---- snow ----
        const float flux_ps  = (Tc <= tt) ? P : 0.0f;
        const float flux_pr  = P - flux_ps;
        snow += flux_ps;
        float flux_m = fmaxf(ddf * (Tc - tt), 0.0f);
        flux_m = fminf(flux_m, snow);
        snow = fmaxf(snow - flux_m, NZ);

        // ---- interception ----
        const float flux_pim = flux_pr * one_m_beta;
        const float flux_psm = flux_pr * beta;
        const float flux_pby = flux_psm * one_m_alpha;
        const float flux_pin = flux_psm * alpha;
        xin += flux_pin;
        const float flux_ptf = fmaxf(xin - stor, 0.0f);
        xin = fmaxf(xin - flux_ptf, NZ);
        const float flux_ein = fminf(Ep * beta, xin);
        xin = fmaxf(xin - flux_ein, NZ);

        // ---- impervious storage ----
        rstor += fmaf(flux_m, one_m_beta, flux_pim);
        const float flux_sas = fmaxf(rstor - retip, 0.0f);
        rstor = fmaxf(rstor - flux_sas, NZ);
        const float flux_eim = fminf(one_m_beta * Ep, rstor);
        rstor = fmaxf(rstor - flux_eim, NZ);

        // ---- surface runoff / recharge ----
        const float sro_lin = fminf(fmaxf(fmaf(c2, rechr, scn), 0.0f), 1.0f);
        const float inflow  = fmaf(flux_m, beta, flux_ptf) + flux_pby;
        const float flux_sro = sro_lin * inflow;
        const float flux_inf = inflow - flux_sro;
        rechr += flux_inf;
        const float flux_pc = fmaxf(rechr - remx, 0.0f);
        rechr -= flux_pc;
        const float ep_net = Ep - flux_ein - flux_eim;
        const float evap_max_a = fmaxf(rechr * inv_remx * ep_net, 0.0f);
        const float flux_ea = fminf(evap_max_a, rechr);
        rechr = fmaxf(rechr - flux_ea, NZ);

        // ---- soil moisture ----
        smav += flux_pc;
        const float flux_excs = fmaxf(smav - smax, 0.0f);
        smav -= flux_excs;
        float transp = (rechr < ep_net)
                         ? fmaxf(smav * inv_smax * (ep_net - flux_ea), 0.0f)
                         : 0.0f;
        transp = fminf(transp, smav);
        smav = fmaxf(smav - transp, NZ);

        // ---- reservoir ----
        const float flux_sep  = fminf(cgw, flux_excs);
        const float flux_qres = fmaxf(flux_excs - flux_sep, 0.0f);
        res += flux_qres;
        const float ratio = res * inv_resmax;
        float flux_gad = exp2f(fmaf(k2, __log2f(ratio), lg2k1));  // == k1 * ratio^k2
        flux_gad = fminf(flux_gad, res);
        res = fmaxf(res - flux_gad, NZ);
        float flux_ras = fminf(fmaf(k4 * res, res, k3 * res), res);
        res = fmaxf(res - flux_ras, NZ);

        // ---- groundwater ----
        gw += flux_gad + flux_sep;
        const float flux_bas = k5 * gw;
        gw = fmaxf(gw - flux_bas, NZ);
        const float flux_snk = k6 * gw;
        gw = fmaxf(gw - flux_snk, NZ);

        // ---- streamflow ----
        *op = flux_sas + flux_sro + flux_bas + flux_ras;
        op += N_GRID;
    }
}

extern "C" void kernel_launch(void* const* d_in, const int* in_sizes, int n_in,
                              void* d_out, int out_size) {
    // Identify inputs by element count (robust to ordering):
    //   x:          730*8000*3  = 17,520,000
    //   parameters: 730*8000*18 = 105,120,000
    const float* x = nullptr;
    const float* params = nullptr;
    for (int i = 0; i < n_in; i++) {
        if (in_sizes[i] == T_STEPS * N_GRID * 3)  x = (const float*)d_in[i];
        if (in_sizes[i] == T_STEPS * N_GRID * 18) params = (const float*)d_in[i];
    }
    float* out = (float*)d_out;

    const int threads = 64;
    const int blocks = (N_GRID + threads - 1) / threads;  // 125 blocks
    prms_kernel<<<blocks, threads>>>(x, params, out);
}

// round 9
// speedup vs baseline: 1.7124x; 1.0387x over previous
#include <cuda_runtime.h>

#define T_STEPS 730
#define N_GRID  8000
#define NZ      1e-5f

__constant__ float c_LO[18] = {-3.f, 0.f, 0.f, 0.f, 0.f, 0.f, 0.f, 0.f, 0.005f, 1.f, 0.f, 1.f, 0.f, 1.f, 0.f, 0.f, 0.f, 0.f};
__constant__ float c_HI[18] = { 5.f,20.f, 1.f, 1.f, 5.f,50.f, 1.f, 1.f, 0.995f, 2000.f, 20.f, 300.f, 1.f, 5.f, 1.f, 1.f, 1.f, 1.f};

__global__ __launch_bounds__(64) void prms_kernel(
    const float* __restrict__ x,      // [T_STEPS, N_GRID, 3]
    const float* __restrict__ params, // [T_STEPS, N_GRID, 18]
    float* __restrict__ out)          // [T_STEPS, N_GRID]
{
    const int g = blockIdx.x * blockDim.x + threadIdx.x;
    if (g >= N_GRID) return;

    // ---- per-cell parameters from the LAST timestep slice ----
    const float* pp = params + ((size_t)(T_STEPS - 1) * N_GRID + g) * 18;
    float pr[18];
#pragma unroll
    for (int i = 0; i < 18; i++) {
        float s = 1.0f / (1.0f + expf(-pp[i]));
        pr[i] = c_LO[i] + s * (c_HI[i] - c_LO[i]);
    }
    const float tt     = pr[0],  ddf   = pr[1],  alpha = pr[2],  beta  = pr[3];
    const float stor   = pr[4],  retip = pr[5],  fscn  = pr[6],  scx   = pr[7];
    const float flz    = pr[8],  stot  = pr[9],  cgw   = pr[10], resmax= pr[11];
    const float k1     = pr[12], k2    = pr[13], k3    = pr[14], k4    = pr[15];
    const float k5     = pr[16], k6    = pr[17];

    const float scn        = fscn * scx;
    const float remx       = (1.0f - flz) * stot;
    const float smax       = flz * stot;
    const float inv_remx   = 1.0f / remx;
    const float inv_smax   = 1.0f / smax;
    const float inv_resmax = 1.0f / resmax;
    const float one_m_beta = 1.0f - beta;
    const float one_m_alpha= 1.0f - alpha;
    const float c2         = (scx - scn) * inv_remx;   // sro_lin slope
    const float lg2k1      = log2f(k1);                // fold k1 into pow exponent

    // ---- state (upper: snow..smav ; lower: res, gw) ----
    float snow = 0.001f, xin = 0.001f, rstor = 0.001f, rechr = 0.001f, smav = 0.001f;
    float res = 0.001f, gw = 0.001f;

    // ---- depth-2 register prefetch pipeline for x ----
    float Pb[2], Tb[2], Eb[2];
    {
        const float* x0 = x + (size_t)g * 3;                      // t = 0
        Pb[0] = x0[0]; Tb[0] = x0[1]; Eb[0] = x0[2];
        const float* x1 = x + ((size_t)N_GRID + g) * 3;           // t = 1
        Pb[1] = x1[0]; Tb[1] = x1[1]; Eb[1] = x1[2];
    }
    const float* xp = x + ((size_t)2 * N_GRID + g) * 3;   // x[t+2] walker
    float*       op = out + g;                            // out[t-1] walker

    // pipeline carries: outputs of upper(t) consumed by lower(t) next iter
    float sas_c, sro_c, excs_c;

    // =================== upper(t) ===================
    auto upper = [&](float P, float Tc, float Ep,
                     float& sas_o, float& sro_o, float& excs_o) {
        // ---- snow ----
        const float flux_ps  = (Tc <= tt) ? P : 0.0f;
        const float flux_pr  = P - flux_ps;
        snow += flux_ps;
        float flux_m = fmaxf(ddf * (Tc - tt), 0.0f);
        flux_m = fminf(flux_m, snow);
        snow = fmaxf(snow - flux_m, NZ);

        // ---- interception ----
        const float flux_pim = flux_pr * one_m_beta;
        const float flux_psm = flux_pr * beta;
        const float flux_pby = flux_psm * one_m_alpha;
        const float flux_pin = flux_psm * alpha;
        xin += flux_pin;
        const float flux_ptf = fmaxf(xin - stor, 0.0f);
        xin = fmaxf(xin - flux_ptf, NZ);
        const float flux_ein = fminf(Ep * beta, xin);
        xin = fmaxf(xin - flux_ein, NZ);

        // ---- impervious storage ----
        rstor += fmaf(flux_m, one_m_beta, flux_pim);
        const float flux_sas = fmaxf(rstor - retip, 0.0f);
        rstor = fmaxf(rstor - flux_sas, NZ);
        const float flux_eim = fminf(one_m_beta * Ep, rstor);
        rstor = fmaxf(rstor - flux_eim, NZ);

        // ---- surface runoff / recharge ----
        const float sro_lin = fminf(fmaxf(fmaf(c2, rechr, scn), 0.0f), 1.0f);
        const float inflow  = fmaf(flux_m, beta, flux_ptf) + flux_pby;
        const float flux_sro = sro_lin * inflow;
        const float flux_inf = inflow - flux_sro;
        rechr += flux_inf;
        const float flux_pc = fmaxf(rechr - remx, 0.0f);
        rechr -= flux_pc;
        const float ep_net = Ep - flux_ein - flux_eim;
        const float evap_max_a = fmaxf(rechr * inv_remx * ep_net, 0.0f);
        const float flux_ea = fminf(evap_max_a, rechr);
        rechr = fmaxf(rechr - flux_ea, NZ);

        // ---- soil moisture ----
        smav += flux_pc;
        const float flux_excs = fmaxf(smav - smax, 0.0f);
        smav -= flux_excs;
        float transp = (rechr < ep_net)
                         ? fmaxf(smav * inv_smax * (ep_net - flux_ea), 0.0f)
                         : 0.0f;
        transp = fminf(transp, smav);
        smav = fmaxf(smav - transp, NZ);

        sas_o = flux_sas; sro_o = flux_sro; excs_o = flux_excs;
    };

    // =================== lower(t) ===================
    auto lower = [&](float flux_sas, float flux_sro, float flux_excs) -> float {
        const float flux_sep  = fminf(cgw, flux_excs);
        const float flux_qres = fmaxf(flux_excs - flux_sep, 0.0f);
        res += flux_qres;
        const float ratio = res * inv_resmax;
        float flux_gad = exp2f(fmaf(k2, __log2f(ratio), lg2k1));  // == k1*ratio^k2
        flux_gad = fminf(flux_gad, res);
        res = fmaxf(res - flux_gad, NZ);
        float flux_ras = fminf(fmaf(k4 * res, res, k3 * res), res);
        res = fmaxf(res - flux_ras, NZ);

        gw += flux_gad + flux_sep;
        const float flux_bas = k5 * gw;
        gw = fmaxf(gw - flux_bas, NZ);
        const float flux_snk = k6 * gw;
        gw = fmaxf(gw - flux_snk, NZ);

        return flux_sas + flux_sro + flux_bas + flux_ras;
    };

    // ---- prologue: FULL t=0 iteration (read slot 0, prefetch x[2] into slot 0,
    //      advance xp) — this was the R8 bug: skipping this desynced the buffer ----
    {
        const float P = Pb[0], Tc = Tb[0], Ep = Eb[0];
        Pb[0] = xp[0]; Tb[0] = xp[1]; Eb[0] = xp[2];      // x[2] -> slot 0
        xp += (size_t)N_GRID * 3;                          // xp now at x[3]
        upper(P, Tc, Ep, sas_c, sro_c, excs_c);
    }

    // ---- pipelined main loop: lower(t-1) || upper(t), t = 1..T-1 ----
#pragma unroll 2
    for (int t = 1; t < T_STEPS; t++) {
        const int b = t & 1;
        const float P  = Pb[b];
        const float Tc = Tb[b];
        const float Ep = Eb[b];
        if (t + 2 < T_STEPS) {                // prefetch x[t+2] into slot b
            Pb[b] = xp[0]; Tb[b] = xp[1]; Eb[b] = xp[2];
        }
        xp += (size_t)N_GRID * 3;             // advance EVERY iteration (R7 indexing)

        // lower chain for step t-1 (independent of upper(t); scheduler interleaves)
        const float q_prev = lower(sas_c, sro_c, excs_c);

        // upper chain for step t
        float sas_n, sro_n, excs_n;
        upper(P, Tc, Ep, sas_n, sro_n, excs_n);

        *op = q_prev;                          // out[t-1]
        op += N_GRID;

        sas_c = sas_n; sro_c = sro_n; excs_c = excs_n;
    }

    // ---- epilogue: lower(T-1) ----
    *op = lower(sas_c, sro_c, excs_c);
}

extern "C" void kernel_launch(void* const* d_in, const int* in_sizes, int n_in,
                              void* d_out, int out_size) {
    // Identify inputs by element count (robust to ordering):
    //   x:          730*8000*3  = 17,520,000
    //   parameters: 730*8000*18 = 105,120,000
    const float* x = nullptr;
    const float* params = nullptr;
    for (int i = 0; i < n_in; i++) {
        if (in_sizes[i] == T_STEPS * N_GRID * 3)  x = (const float*)d_in[i];
        if (in_sizes[i] == T_STEPS * N_GRID * 18) params = (const float*)d_in[i];
    }
    float* out = (float*)d_out;

    const int threads = 64;
    const int blocks = (N_GRID + threads - 1) / threads;  // 125 blocks
    prms_kernel<<<blocks, threads>>>(x, params, out);
}

// round 10
// speedup vs baseline: 2.1005x; 1.2266x over previous
#include <cuda_runtime.h>

#define T_STEPS 730
#define N_GRID  8000
#define NZ      1e-5f

__constant__ float c_LO[18] = {-3.f, 0.f, 0.f, 0.f, 0.f, 0.f, 0.f, 0.f, 0.005f, 1.f, 0.f, 1.f, 0.f, 1.f, 0.f, 0.f, 0.f, 0.f};
__constant__ float c_HI[18] = { 5.f,20.f, 1.f, 1.f, 5.f,50.f, 1.f, 1.f, 0.995f, 2000.f, 20.f, 300.f, 1.f, 5.f, 1.f, 1.f, 1.f, 1.f};

__device__ __forceinline__ float fast_ex2(float a) {
    float r;
    asm("ex2.approx.f32 %0, %1;" : "=f"(r) : "f"(a));
    return r;
}

__global__ __launch_bounds__(64) void prms_kernel(
    const float* __restrict__ x,      // [T_STEPS, N_GRID, 3]
    const float* __restrict__ params, // [T_STEPS, N_GRID, 18]
    float* __restrict__ out)          // [T_STEPS, N_GRID]
{
    const int g = blockIdx.x * blockDim.x + threadIdx.x;
    if (g >= N_GRID) return;

    // ---- per-cell parameters from the LAST timestep slice ----
    const float* pp = params + ((size_t)(T_STEPS - 1) * N_GRID + g) * 18;
    float pr[18];
#pragma unroll
    for (int i = 0; i < 18; i++) {
        float s = 1.0f / (1.0f + expf(-pp[i]));
        pr[i] = c_LO[i] + s * (c_HI[i] - c_LO[i]);
    }
    const float tt     = pr[0],  ddf   = pr[1],  alpha = pr[2],  beta  = pr[3];
    const float stor   = pr[4],  retip = pr[5],  fscn  = pr[6],  scx   = pr[7];
    const float flz    = pr[8],  stot  = pr[9],  cgw   = pr[10], resmax= pr[11];
    const float k1     = pr[12], k2    = pr[13], k3    = pr[14], k4    = pr[15];
    const float k5     = pr[16], k6    = pr[17];

    const float scn        = fscn * scx;
    const float remx       = (1.0f - flz) * stot;
    const float smax       = flz * stot;
    const float inv_remx   = 1.0f / remx;
    const float inv_smax   = 1.0f / smax;
    const float inv_resmax = 1.0f / resmax;
    const float one_m_beta = 1.0f - beta;
    const float one_m_alpha= 1.0f - alpha;
    const float c2         = (scx - scn) * inv_remx;   // sro_lin slope
    const float lg2k1      = log2f(k1);                // fold k1 into pow exponent

    // ---- state (upper: snow..smav ; lower: res, gw) ----
    float snow = 0.001f, xin = 0.001f, rstor = 0.001f, rechr = 0.001f, smav = 0.001f;
    float res = 0.001f, gw = 0.001f;

    // ---- depth-2 register prefetch pipeline for x ----
    float Pb[2], Tb[2], Eb[2];
    {
        const float* x0 = x + (size_t)g * 3;                      // t = 0
        Pb[0] = x0[0]; Tb[0] = x0[1]; Eb[0] = x0[2];
        const float* x1 = x + ((size_t)N_GRID + g) * 3;           // t = 1
        Pb[1] = x1[0]; Tb[1] = x1[1]; Eb[1] = x1[2];
    }
    const float* xp = x + ((size_t)2 * N_GRID + g) * 3;   // x[t+2] walker
    float*       op = out + g;                            // out[t-1] walker

    // pipeline carries: outputs of upper(t) consumed by lower(t) next iter
    float sas_c, sro_c, excs_c;

    // =================== upper(t) ===================
    auto upper = [&](float P, float Tc, float Ep,
                     float& sas_o, float& sro_o, float& excs_o) {
        // ---- snow (clamp lemma: drop the min from the self-loop) ----
        const float flux_ps  = (Tc <= tt) ? P : 0.0f;
        const float flux_pr  = P - flux_ps;
        const float snow1    = snow + flux_ps;
        const float mpot     = fmaxf(ddf * (Tc - tt), 0.0f);
        const float flux_m   = fminf(mpot, snow1);             // still needed downstream
        snow = fmaxf(snow1 - mpot, NZ);                        // == max(snow1-flux_m, NZ)

        // ---- interception (lemmas on both clamps) ----
        const float flux_pim = flux_pr * one_m_beta;
        const float flux_psm = flux_pr * beta;
        const float flux_pby = flux_psm * one_m_alpha;
        const float flux_pin = flux_psm * alpha;
        const float xin1 = xin + flux_pin;
        const float flux_ptf = fmaxf(xin1 - stor, 0.0f);
        const float xin2 = fminf(xin1, stor);                  // == max(xin1-ptf, ...) clamped
        const float epb  = Ep * beta;
        const float flux_ein = fminf(epb, xin2);
        xin = fmaxf(xin2 - epb, NZ);                           // lemma

        // ---- impervious storage (lemmas) ----
        const float rs1 = rstor + fmaf(flux_m, one_m_beta, flux_pim);
        const float flux_sas = fmaxf(rs1 - retip, 0.0f);
        const float rs2 = fminf(rs1, retip);
        const float eib = one_m_beta * Ep;
        const float flux_eim = fminf(eib, rs2);
        rstor = fmaxf(rs2 - eib, NZ);                          // lemma

        // ---- surface runoff / recharge ----
        const float sro_lin = fminf(fmaxf(fmaf(c2, rechr, scn), 0.0f), 1.0f);
        const float inflow  = fmaf(flux_m, beta, flux_ptf) + flux_pby;
        const float flux_sro = sro_lin * inflow;
        const float flux_inf = inflow - flux_sro;
        const float re1 = rechr + flux_inf;
        const float flux_pc = fmaxf(re1 - remx, 0.0f);
        const float re2 = fminf(re1, remx);                    // lemma
        const float ep_net = Ep - flux_ein - flux_eim;         // >= 0 always
        const float evap_max_a = re2 * inv_remx * ep_net;      // >= 0, max(.,0) redundant
        const float flux_ea = fminf(evap_max_a, re2);
        rechr = fmaxf(re2 - flux_ea, NZ);

        // ---- soil moisture (lemma on excs clamp) ----
        const float sm1 = smav + flux_pc;
        const float flux_excs = fmaxf(sm1 - smax, 0.0f);
        const float sm2 = fminf(sm1, smax);
        float transp = (rechr < ep_net)
                         ? fminf(fmaxf(sm2 * inv_smax * (ep_net - flux_ea), 0.0f), sm2)
                         : 0.0f;
        smav = fmaxf(sm2 - transp, NZ);

        sas_o = flux_sas; sro_o = flux_sro; excs_o = flux_excs;
    };

    // =================== lower(t) ===================
    auto lower = [&](float flux_sas, float flux_sro, float flux_excs) -> float {
        const float flux_sep  = fminf(cgw, flux_excs);
        const float flux_qres = flux_excs - flux_sep;          // >= 0 exactly
        res += flux_qres;
        const float ratio = res * inv_resmax;
        float flux_gad = fast_ex2(fmaf(k2, __log2f(ratio), lg2k1));  // == k1*ratio^k2, MUFU pair
        flux_gad = fminf(flux_gad, res);
        res = fmaxf(res - flux_gad, NZ);
        float flux_ras = fminf(fmaf(k4 * res, res, k3 * res), res);
        res = fmaxf(res - flux_ras, NZ);

        gw += flux_gad + flux_sep;
        const float flux_bas = k5 * gw;
        gw = fmaxf(gw - flux_bas, NZ);
        const float flux_snk = k6 * gw;
        gw = fmaxf(gw - flux_snk, NZ);

        return flux_sas + flux_sro + flux_bas + flux_ras;
    };

    // ---- prologue: FULL t=0 iteration (read slot 0, prefetch x[2] -> slot 0) ----
    {
        const float P = Pb[0], Tc = Tb[0], Ep = Eb[0];
        Pb[0] = xp[0]; Tb[0] = xp[1]; Eb[0] = xp[2];      // x[2] -> slot 0
        xp += (size_t)N_GRID * 3;                          // xp now at x[3]
        upper(P, Tc, Ep, sas_c, sro_c, excs_c);
    }

    // ---- pipelined main loop: lower(t-1) || upper(t), t = 1..T-1 ----
#pragma unroll 2
    for (int t = 1; t < T_STEPS; t++) {
        const int b = t & 1;
        const float P  = Pb[b];
        const float Tc = Tb[b];
        const float Ep = Eb[b];
        if (t + 2 < T_STEPS) {                // prefetch x[t+2] into slot b
            Pb[b] = xp[0]; Tb[b] = xp[1]; Eb[b] = xp[2];
        }
        xp += (size_t)N_GRID * 3;             // advance EVERY iteration

        // lower chain for step t-1 (independent of upper(t); scheduler interleaves)
        const float q_prev = lower(sas_c, sro_c, excs_c);

        // upper chain for step t
        float sas_n, sro_n, excs_n;
        upper(P, Tc, Ep, sas_n, sro_n, excs_n);

        *op = q_prev;                          // out[t-1]
        op += N_GRID;

        sas_c = sas_n; sro_c = sro_n; excs_c = excs_n;
    }

    // ---- epilogue: lower(T-1) ----
    *op = lower(sas_c, sro_c, excs_c);
}

extern "C" void kernel_launch(void* const* d_in, const int* in_sizes, int n_in,
                              void* d_out, int out_size) {
    // Identify inputs by element count (robust to ordering):
    //   x:          730*8000*3  = 17,520,000
    //   parameters: 730*8000*18 = 105,120,000
    const float* x = nullptr;
    const float* params = nullptr;
    for (int i = 0; i < n_in; i++) {
        if (in_sizes[i] == T_STEPS * N_GRID * 3)  x = (const float*)d_in[i];
        if (in_sizes[i] == T_STEPS * N_GRID * 18) params = (const float*)d_in[i];
    }
    float* out = (float*)d_out;

    const int threads = 64;
    const int blocks = (N_GRID + threads - 1) / threads;  // 125 blocks
    prms_kernel<<<blocks, threads>>>(x, params, out);
}